// round 3
// baseline (speedup 1.0000x reference)
#include <cuda_runtime.h>
#include <math.h>

#define LMAX 20
#define NM   21           // number of m columns (0..20)
#define KVAL 441          // (LMAX+1)^2
#define RANK_ 256
#define BPTS 16           // points per CTA
#define NTHREADS 256

// --------------------------------------------------------------------------
// Precomputed recurrence tables (filled by init kernel, double precision).
// Semi-normalized Legendre:  Q(l,m) = norm(l,m) * [sqrt2 if m>0] * P(l,m)
//   Q(m,m)   = g_seed[m] * pmm           (pmm = prod_{k=1..m} -(2k-1) sin)
//   Q(m+1,m) = g_c1[m] * ct * Q(m,m)
//   Q(l,m)   = g_A[l,m] * ct * Q(l-1,m) - g_B[l,m] * Q(l-2,m)
// --------------------------------------------------------------------------
__device__ float g_A[NM * NM];
__device__ float g_B[NM * NM];
__device__ float g_seed[NM];
__device__ float g_c1[NM];

__device__ __forceinline__ double normd(int l, int m) {
    double r = (2.0 * l + 1.0) / (4.0 * 3.14159265358979323846);
    for (int k = l - m + 1; k <= l + m; ++k) r /= (double)k;   // *(l-m)!/(l+m)!
    return sqrt(r);
}

__global__ void init_tables_kernel() {
    int i = threadIdx.x;
    if (i < NM) {
        int m = i;
        double s = normd(m, m);
        if (m > 0) s *= 1.4142135623730951;   // sqrt(2) for m != 0 terms
        g_seed[m] = (float)s;
        g_c1[m] = (m < LMAX)
            ? (float)((2.0 * m + 1.0) * normd(m + 1, m) / normd(m, m))
            : 0.f;
    }
    for (int idx = i; idx < NM * NM; idx += blockDim.x) {
        int l = idx / NM, m = idx % NM;
        if (l >= m + 2) {
            g_A[idx] = (float)((2.0 * l - 1.0) / (double)(l - m)
                               * normd(l, m) / normd(l - 1, m));
            g_B[idx] = (float)((double)(l + m - 1) / (double)(l - m)
                               * normd(l, m) / normd(l - 2, m));
        } else {
            g_A[idx] = 0.f; g_B[idx] = 0.f;
        }
    }
}

// --------------------------------------------------------------------------
// Main kernel: one CTA handles BPTS points.
// Phase 0: per (point,vector) compute ct plus cos(m a), sin(m a), pmm chains.
// Phase 1: 672 tasks (point x vector x m-column), stream Y values into smem.
// Phase 2: coalesced gathered-product output.
// --------------------------------------------------------------------------
__global__ __launch_bounds__(NTHREADS, 1) void sh_kernel(
    const float* __restrict__ coords, const int* __restrict__ ri,
    const int* __restrict__ rj, float* __restrict__ out, int npts)
{
    extern __shared__ float smem[];
    float* s_psi  = smem;                          // BPTS*2*KVAL
    float* s_pv   = s_psi + BPTS * 2 * KVAL;       // BPTS*2 * 64
    float* s_A    = s_pv + BPTS * 2 * 64;          // 441
    float* s_B    = s_A + NM * NM;                 // 441
    float* s_seed = s_B + NM * NM;                 // 21
    float* s_c1   = s_seed + NM;                   // 21
    int*   s_ri   = (int*)(s_c1 + NM);             // 256
    int*   s_rj   = s_ri + RANK_;                  // 256

    const int t  = threadIdx.x;
    const int p0 = blockIdx.x * BPTS;

    // Stage rank indices and recurrence tables.
    s_ri[t] = ri[t];
    s_rj[t] = rj[t];
    for (int idx = t; idx < NM * NM; idx += NTHREADS) {
        s_A[idx] = g_A[idx];
        s_B[idx] = g_B[idx];
    }
    if (t < NM) { s_seed[t] = g_seed[t]; s_c1[t] = g_c1[t]; }

    // Phase 0: per (point, vector) trig / diagonal chains (32 threads).
    if (t < BPTS * 2) {
        int p = t >> 1, v = t & 1;
        float ct = 0.f, st = 0.f, ca = 1.f, sa = 0.f;
        if (p0 + p < npts) {
            const float* cp = coords + (size_t)(p0 + p) * 6 + v * 3;
            float X = cp[0], Yc = cp[1], Z = cp[2];
            float r = sqrtf(X * X + Yc * Yc + Z * Z);
            ct = Z / r;
            ct = fminf(1.f, fmaxf(-1.f, ct));
            st = sqrtf(fmaxf(0.f, 1.f - ct * ct));     // sin(arccos(ct)) >= 0
            float rxy2 = X * X + Yc * Yc;
            if (rxy2 > 0.f) {                          // atan2(0,0)=0 -> ca=1,sa=0
                float irxy = rsqrtf(rxy2);
                ca = X * irxy; sa = Yc * irxy;
            }
        }
        float* pvd = s_pv + t * 64;
        pvd[0] = ct;
        float cm = 1.f, sv = 0.f, pm = 1.f;
        pvd[1] = cm; pvd[22] = sv; pvd[43] = pm;
        #pragma unroll
        for (int m = 1; m <= LMAX; ++m) {
            float cn = cm * ca - sv * sa;              // cos(m a)
            sv = cm * sa + sv * ca;                    // sin(m a)
            cm = cn;
            pm *= (1.f - 2.f * (float)m) * st;         // Condon-Shortley diag
            pvd[1 + m] = cm; pvd[22 + m] = sv; pvd[43 + m] = pm;
        }
    }
    __syncthreads();

    // Phase 1: one task per (point, vector, m-column).
    for (int task = t; task < BPTS * 2 * NM; task += NTHREADS) {
        int m  = task % NM;
        int pv = task / NM;
        if (p0 + (pv >> 1) >= npts) continue;
        const float* pvd = s_pv + pv * 64;
        float ct = pvd[0];
        float cm = pvd[1 + m], sv = pvd[22 + m], pm = pvd[43 + m];
        float* ps = s_psi + pv * KVAL;

        float q2 = s_seed[m] * pm;                     // l = m
        int base = m * (m + 1);
        // For m==0: sv==0 then cm==1 overwrites same address -> correct.
        ps[base - m] = q2 * sv;
        ps[base + m] = q2 * cm;
        if (m < LMAX) {
            float q1 = s_c1[m] * ct * q2;              // l = m+1
            base = (m + 1) * (m + 2);
            ps[base - m] = q1 * sv;
            ps[base + m] = q1 * cm;
            for (int l = m + 2; l <= LMAX; ++l) {
                float qn = s_A[l * NM + m] * ct * q1 - s_B[l * NM + m] * q2;
                q2 = q1; q1 = qn;
                base = l * (l + 1);
                ps[base - m] = qn * sv;
                ps[base + m] = qn * cm;
            }
        }
    }
    __syncthreads();

    // Phase 2: gathered products, coalesced stores.
    for (int o = t; o < BPTS * RANK_; o += NTHREADS) {
        int p = o >> 8;
        int r = o & (RANK_ - 1);
        int gp = p0 + p;
        if (gp < npts) {
            float a = s_psi[(2 * p)     * KVAL + s_ri[r]];
            float b = s_psi[(2 * p + 1) * KVAL + s_rj[r]];
            out[(size_t)gp * RANK_ + r] = a * b;
        }
    }
}

extern "C" void kernel_launch(void* const* d_in, const int* in_sizes, int n_in,
                              void* d_out, int out_size) {
    const float* coords = (const float*)d_in[0];
    const int*   ri     = (const int*)d_in[1];
    const int*   rj     = (const int*)d_in[2];
    float*       out    = (float*)d_out;
    int npts = in_sizes[0] / 6;

    const size_t SMEM = (size_t)(BPTS * 2 * KVAL    // psi
                                 + BPTS * 2 * 64    // per-(p,v) chains
                                 + 2 * NM * NM      // A, B
                                 + 2 * NM           // seed, c1
                                 + 2 * RANK_)       // ri, rj
                        * sizeof(float);
    cudaFuncSetAttribute((const void*)sh_kernel,
                         cudaFuncAttributeMaxDynamicSharedMemorySize, (int)SMEM);

    init_tables_kernel<<<1, 512>>>();
    int grid = (npts + BPTS - 1) / BPTS;
    sh_kernel<<<grid, NTHREADS, SMEM>>>(coords, ri, rj, out, npts);
}

// round 6
// speedup vs baseline: 2.0871x; 2.0871x over previous
#include <cuda_runtime.h>
#include <math.h>

#define LMAX 20
#define NM   21           // number of m columns (0..20)
#define KVAL 441          // (LMAX+1)^2
#define RANK_ 256
#define BPTS 16           // points per CTA
#define NPV  (BPTS * 2)   // 32 (point,vector) pairs
#define NTHREADS 256
#define PV_STRIDE 65      // padded (coprime with 32 banks)

// --------------------------------------------------------------------------
// Precomputed recurrence tables — SAME FORMULAS as the known-good round-2
// kernel, only the factorial ratio is computed as a product then one divide
// (instead of a chain of double divisions) to make init fast.
// Semi-normalized Legendre:  Q(l,m) = norm(l,m) * [sqrt2 if m>0] * P(l,m)
//   Q(m,m)   = g_seed[m] * pmm           (pmm = prod_{k=1..m} -(2k-1) sin)
//   Q(m+1,m) = g_c1[m] * ct * Q(m,m)
//   Q(l,m)   = g_A[l,m] * ct * Q(l-1,m) - g_B[l,m] * Q(l-2,m)
// --------------------------------------------------------------------------
__device__ float g_A[NM * NM];
__device__ float g_B[NM * NM];
__device__ float g_seed[NM];
__device__ float g_c1[NM];

__device__ __forceinline__ double normd(int l, int m) {
    // sqrt( (2l+1)/(4pi) * (l-m)!/(l+m)! )
    double p = 1.0;
    for (int k = l - m + 1; k <= l + m; ++k) p *= (double)k;  // (l+m)!/(l-m)!
    return sqrt((2.0 * l + 1.0) / (4.0 * 3.14159265358979323846) / p);
}

__global__ void init_tables_kernel() {
    int i = threadIdx.x;
    if (i < NM) {
        int m = i;
        double s = normd(m, m);
        if (m > 0) s *= 1.4142135623730951;   // sqrt(2) for m != 0 terms
        g_seed[m] = (float)s;
        g_c1[m] = (m < LMAX)
            ? (float)((2.0 * m + 1.0) * normd(m + 1, m) / normd(m, m))
            : 0.f;
    }
    for (int idx = i; idx < NM * NM; idx += blockDim.x) {
        int l = idx / NM, m = idx % NM;
        if (l >= m + 2) {
            g_A[idx] = (float)((2.0 * l - 1.0) / (double)(l - m)
                               * normd(l, m) / normd(l - 1, m));
            g_B[idx] = (float)((double)(l + m - 1) / (double)(l - m)
                               * normd(l, m) / normd(l - 2, m));
        } else {
            g_A[idx] = 0.f; g_B[idx] = 0.f;
        }
    }
}

// --------------------------------------------------------------------------
// Main kernel: one CTA handles BPTS points (= 32 (point,vector) pairs).
// Phase 0: per (point,vector) ct + cos(m a), sin(m a), pmm chains.
// Phase 1: 672 tasks; task -> (pv = task & 31, m = task >> 5) so each warp
//          gets a uniform m (lane = pv): no divergence, broadcast tables.
// Phase 2: coalesced gathered-product output (round-2 verbatim).
// --------------------------------------------------------------------------
__global__ __launch_bounds__(NTHREADS, 1) void sh_kernel(
    const float* __restrict__ coords, const int* __restrict__ ri,
    const int* __restrict__ rj, float* __restrict__ out, int npts)
{
    extern __shared__ float smem[];
    float* s_psi  = smem;                          // NPV*KVAL
    float* s_pv   = s_psi + NPV * KVAL;            // NPV*PV_STRIDE
    float* s_A    = s_pv + NPV * PV_STRIDE;        // 441
    float* s_B    = s_A + NM * NM;                 // 441
    float* s_seed = s_B + NM * NM;                 // 21
    float* s_c1   = s_seed + NM;                   // 21
    int*   s_ri   = (int*)(s_c1 + NM);             // 256
    int*   s_rj   = s_ri + RANK_;                  // 256

    const int t  = threadIdx.x;
    const int p0 = blockIdx.x * BPTS;

    // Stage rank indices and recurrence tables.
    s_ri[t] = ri[t];
    s_rj[t] = rj[t];
    for (int idx = t; idx < NM * NM; idx += NTHREADS) {
        s_A[idx] = g_A[idx];
        s_B[idx] = g_B[idx];
    }
    if (t < NM) { s_seed[t] = g_seed[t]; s_c1[t] = g_c1[t]; }

    // Phase 0: per (point, vector) trig / diagonal chains (32 threads).
    if (t < NPV) {
        int p = t >> 1, v = t & 1;
        float ct = 0.f, st = 0.f, ca = 1.f, sa = 0.f;
        if (p0 + p < npts) {
            const float* cp = coords + (size_t)(p0 + p) * 6 + v * 3;
            float X = cp[0], Yc = cp[1], Z = cp[2];
            float r = sqrtf(X * X + Yc * Yc + Z * Z);
            ct = Z / r;
            ct = fminf(1.f, fmaxf(-1.f, ct));
            st = sqrtf(fmaxf(0.f, 1.f - ct * ct));     // sin(arccos(ct)) >= 0
            float rxy2 = X * X + Yc * Yc;
            if (rxy2 > 0.f) {                          // atan2(0,0)=0 -> ca=1,sa=0
                float irxy = rsqrtf(rxy2);
                ca = X * irxy; sa = Yc * irxy;
            }
        }
        float* pvd = s_pv + t * PV_STRIDE;
        pvd[0] = ct;
        float cm = 1.f, sv = 0.f, pm = 1.f;
        pvd[1] = cm; pvd[22] = sv; pvd[43] = pm;
        #pragma unroll
        for (int m = 1; m <= LMAX; ++m) {
            float cn = cm * ca - sv * sa;              // cos(m*azim)
            sv = cm * sa + sv * ca;                    // sin(m*azim)
            cm = cn;
            pm *= (1.f - 2.f * (float)m) * st;         // Condon-Shortley diag
            pvd[1 + m] = cm; pvd[22 + m] = sv; pvd[43 + m] = pm;
        }
    }
    __syncthreads();

    // Phase 1: one task per (point, vector, m-column).
    // Remapped so lane = pv and m is warp-uniform (same 672 tasks as before).
    for (int task = t; task < NPV * NM; task += NTHREADS) {
        int pv = task & 31;
        int m  = task >> 5;
        if (p0 + (pv >> 1) >= npts) continue;
        const float* pvd = s_pv + pv * PV_STRIDE;
        float ct = pvd[0];
        float cm = pvd[1 + m], sv = pvd[22 + m], pm = pvd[43 + m];
        float* ps = s_psi + pv * KVAL;

        float q2 = s_seed[m] * pm;                     // l = m
        int base = m * (m + 1);
        // For m==0: sv==0 then cm==1 overwrites same address -> correct.
        ps[base - m] = q2 * sv;
        ps[base + m] = q2 * cm;
        if (m < LMAX) {
            float q1 = s_c1[m] * ct * q2;              // l = m+1
            base = (m + 1) * (m + 2);
            ps[base - m] = q1 * sv;
            ps[base + m] = q1 * cm;
            for (int l = m + 2; l <= LMAX; ++l) {
                float qn = s_A[l * NM + m] * ct * q1 - s_B[l * NM + m] * q2;
                q2 = q1; q1 = qn;
                base = l * (l + 1);
                ps[base - m] = qn * sv;
                ps[base + m] = qn * cm;
            }
        }
    }
    __syncthreads();

    // Phase 2: gathered products, coalesced stores (round-2 verbatim).
    for (int o = t; o < BPTS * RANK_; o += NTHREADS) {
        int p = o >> 8;
        int r = o & (RANK_ - 1);
        int gp = p0 + p;
        if (gp < npts) {
            float a = s_psi[(2 * p)     * KVAL + s_ri[r]];
            float b = s_psi[(2 * p + 1) * KVAL + s_rj[r]];
            out[(size_t)gp * RANK_ + r] = a * b;
        }
    }
}

extern "C" void kernel_launch(void* const* d_in, const int* in_sizes, int n_in,
                              void* d_out, int out_size) {
    const float* coords = (const float*)d_in[0];
    const int*   ri     = (const int*)d_in[1];
    const int*   rj     = (const int*)d_in[2];
    float*       out    = (float*)d_out;
    int npts = in_sizes[0] / 6;

    const size_t SMEM = (size_t)(NPV * KVAL            // psi
                                 + NPV * PV_STRIDE     // chains
                                 + 2 * NM * NM         // A, B
                                 + 2 * NM              // seed, c1
                                 + 2 * RANK_)          // ri, rj
                        * sizeof(float);
    cudaFuncSetAttribute((const void*)sh_kernel,
                         cudaFuncAttributeMaxDynamicSharedMemorySize, (int)SMEM);

    init_tables_kernel<<<1, 512>>>();
    int grid = (npts + BPTS - 1) / BPTS;
    sh_kernel<<<grid, NTHREADS, SMEM>>>(coords, ri, rj, out, npts);
}